// round 1
// baseline (speedup 1.0000x reference)
#include <cuda_runtime.h>
#include <math.h>

#define BB  2
#define TT  2048
#define DD  2048
#define HH  16
#define DHH 128
#define MM  (BB*TT)    // 4096
#define NN  (HH*DHH)   // 2048
#define KK  DD         // 2048

// Scratch (allocation-free rule: __device__ globals)
__device__ float g_q[(size_t)BB*HH*TT*DHH];
__device__ float g_k[(size_t)BB*HH*TT*DHH];
__device__ float g_v[(size_t)BB*HH*TT*DHH];
__device__ float g_o[(size_t)BB*TT*NN];

// ---------------------------------------------------------------------------
// Tiled SGEMM: C = A(MxK) * W + bias.
// mode 0: W is [H, D, Dh] (per-head K-major), output written headed [B,H,T,Dh]
// mode 1: W is [K, N] row-major, output written row-major [M, N]
// BM=BN=128, BK=8, 256 threads, 8x8 per-thread tile.
// ---------------------------------------------------------------------------
__global__ __launch_bounds__(256) void gemm_kernel(
    const float* __restrict__ A, const float* __restrict__ W,
    const float* __restrict__ bias, float* __restrict__ C, int mode)
{
    const int bx  = blockIdx.x;  // n tile (0..15)
    const int by  = blockIdx.y;  // m tile (0..31)
    const int tid = threadIdx.x;

    __shared__ float As[8][128];   // transposed A tile
    __shared__ float Bs[8][128];

    const int m0 = by * 128;
    const float* Aptr = A + (size_t)m0 * KK;
    const float* Bptr;
    int ldb;
    if (mode == 0) { Bptr = W + (size_t)bx * ((size_t)KK * 128); ldb = 128; }
    else           { Bptr = W + bx * 128;                        ldb = NN;  }

    const int ty = tid >> 4;          // 0..15
    const int tx = tid & 15;          // 0..15

    const int arow = tid >> 1;        // 0..127
    const int acol = (tid & 1) * 4;   // 0 or 4
    const int brow = tid >> 5;        // 0..7
    const int bcol = (tid & 31) * 4;  // 0..124

    float acc[8][8];
    #pragma unroll
    for (int i = 0; i < 8; i++)
        #pragma unroll
        for (int j = 0; j < 8; j++) acc[i][j] = 0.f;

    for (int k0 = 0; k0 < KK; k0 += 8) {
        float4 av = *(const float4*)(Aptr + (size_t)arow * KK + k0 + acol);
        As[acol + 0][arow] = av.x;
        As[acol + 1][arow] = av.y;
        As[acol + 2][arow] = av.z;
        As[acol + 3][arow] = av.w;
        float4 bv = *(const float4*)(Bptr + (size_t)(k0 + brow) * ldb + bcol);
        *(float4*)(&Bs[brow][bcol]) = bv;
        __syncthreads();

        #pragma unroll
        for (int k = 0; k < 8; k++) {
            float4 a0 = *(const float4*)(&As[k][ty * 8]);
            float4 a1 = *(const float4*)(&As[k][ty * 8 + 4]);
            float4 b0 = *(const float4*)(&Bs[k][tx * 8]);
            float4 b1 = *(const float4*)(&Bs[k][tx * 8 + 4]);
            float ra[8] = {a0.x, a0.y, a0.z, a0.w, a1.x, a1.y, a1.z, a1.w};
            float rb[8] = {b0.x, b0.y, b0.z, b0.w, b1.x, b1.y, b1.z, b1.w};
            #pragma unroll
            for (int i = 0; i < 8; i++)
                #pragma unroll
                for (int j = 0; j < 8; j++)
                    acc[i][j] += ra[i] * rb[j];
        }
        __syncthreads();
    }

    // Writeback (+bias). n = bx*128 + tx*8 + j
    #pragma unroll
    for (int i = 0; i < 8; i++) {
        const int m = m0 + ty * 8 + i;
        float* dst;
        if (mode == 0) {
            const int b = m >> 11;          // m / T
            const int t = m & (TT - 1);     // m % T
            dst = C + (((size_t)(b * HH + bx)) * TT + t) * DHH + tx * 8;
        } else {
            dst = C + (size_t)m * NN + bx * 128 + tx * 8;
        }
        const float* bptr = bias + bx * 128 + tx * 8;
        #pragma unroll
        for (int j = 0; j < 8; j++) dst[j] = acc[i][j] + bptr[j];
    }
}

// ---------------------------------------------------------------------------
// Causal flash attention, fp32, online softmax.
// Grid: (T/64, B*H). 256 threads. Br=Bc=64.
// Thread map for S: (tr,tc) in 16x16, 4x4 S sub-tile each.
// Thread map for O: rows tr*4+i, cols tc + 16*e (e=0..7).
// ---------------------------------------------------------------------------
__global__ __launch_bounds__(256) void attn_kernel(
    const float* __restrict__ Q, const float* __restrict__ Kg,
    const float* __restrict__ Vg, float* __restrict__ O)
{
    extern __shared__ float sh[];
    float* sQ = sh;                  // [64][129]
    float* sK = sQ + 64 * 129;       // [64][129]
    float* sV = sK + 64 * 129;       // [64][128]
    float* sS = sV + 64 * 128;       // [64][65]

    const int bh  = blockIdx.y;      // b*H + h
    const int q0  = blockIdx.x * 64;
    const int tid = threadIdx.x;
    const int tr  = tid >> 4;        // 0..15
    const int tc  = tid & 15;        // 0..15

    const float scale = 0.08838834764831845f;  // 1/sqrt(128)

    const float* Qb = Q  + (size_t)bh * TT * DHH;
    const float* Kb = Kg + (size_t)bh * TT * DHH;
    const float* Vb = Vg + (size_t)bh * TT * DHH;

    // Load Q tile once
    for (int i = tid; i < 64 * 32; i += 256) {
        const int r = i >> 5, c4 = (i & 31) * 4;
        float4 v = *(const float4*)(Qb + (size_t)(q0 + r) * DHH + c4);
        sQ[r * 129 + c4 + 0] = v.x;
        sQ[r * 129 + c4 + 1] = v.y;
        sQ[r * 129 + c4 + 2] = v.z;
        sQ[r * 129 + c4 + 3] = v.w;
    }

    float m_i[4], l_i[4], accO[4][8];
    #pragma unroll
    for (int i = 0; i < 4; i++) {
        m_i[i] = -INFINITY; l_i[i] = 0.f;
        #pragma unroll
        for (int e = 0; e < 8; e++) accO[i][e] = 0.f;
    }

    const int jend = q0 + 64;
    for (int j0 = 0; j0 < jend; j0 += 64) {
        __syncthreads();  // protect sK/sV/sS from previous iter (and sQ, 1st iter)

        // Load K,V tiles
        for (int i = tid; i < 64 * 32; i += 256) {
            const int r = i >> 5, c4 = (i & 31) * 4;
            float4 kv = *(const float4*)(Kb + (size_t)(j0 + r) * DHH + c4);
            sK[r * 129 + c4 + 0] = kv.x;
            sK[r * 129 + c4 + 1] = kv.y;
            sK[r * 129 + c4 + 2] = kv.z;
            sK[r * 129 + c4 + 3] = kv.w;
            float4 vv = *(const float4*)(Vb + (size_t)(j0 + r) * DHH + c4);
            *(float4*)(sV + r * 128 + c4) = vv;
        }
        __syncthreads();

        // S = Q K^T (4x4 per thread)
        float s[4][4];
        #pragma unroll
        for (int i = 0; i < 4; i++)
            #pragma unroll
            for (int jj = 0; jj < 4; jj++) s[i][jj] = 0.f;

        #pragma unroll 4
        for (int k = 0; k < 128; k++) {
            float qr[4], kr[4];
            #pragma unroll
            for (int i = 0; i < 4; i++)  qr[i]  = sQ[(tr * 4 + i) * 129 + k];
            #pragma unroll
            for (int jj = 0; jj < 4; jj++) kr[jj] = sK[(tc * 4 + jj) * 129 + k];
            #pragma unroll
            for (int i = 0; i < 4; i++)
                #pragma unroll
                for (int jj = 0; jj < 4; jj++)
                    s[i][jj] += qr[i] * kr[jj];
        }

        // scale + causal mask
        #pragma unroll
        for (int i = 0; i < 4; i++) {
            const int qi = q0 + tr * 4 + i;
            #pragma unroll
            for (int jj = 0; jj < 4; jj++) {
                const int kj = j0 + tc * 4 + jj;
                s[i][jj] = (kj <= qi) ? s[i][jj] * scale : -INFINITY;
            }
        }

        // online softmax (rowwise over 16 tc-lanes)
        float alpha[4];
        #pragma unroll
        for (int i = 0; i < 4; i++) {
            float mt = fmaxf(fmaxf(s[i][0], s[i][1]), fmaxf(s[i][2], s[i][3]));
            #pragma unroll
            for (int o = 1; o < 16; o <<= 1)
                mt = fmaxf(mt, __shfl_xor_sync(0xffffffffu, mt, o));
            const float mn = fmaxf(m_i[i], mt);
            alpha[i] = __expf(m_i[i] - mn);
            m_i[i] = mn;
            float ls = 0.f;
            #pragma unroll
            for (int jj = 0; jj < 4; jj++) {
                const float p = __expf(s[i][jj] - mn);
                s[i][jj] = p;
                ls += p;
            }
            #pragma unroll
            for (int o = 1; o < 16; o <<= 1)
                ls += __shfl_xor_sync(0xffffffffu, ls, o);
            l_i[i] = l_i[i] * alpha[i] + ls;
        }

        // P -> shared
        #pragma unroll
        for (int i = 0; i < 4; i++)
            #pragma unroll
            for (int jj = 0; jj < 4; jj++)
                sS[(tr * 4 + i) * 65 + tc * 4 + jj] = s[i][jj];

        // rescale accumulators
        #pragma unroll
        for (int i = 0; i < 4; i++)
            #pragma unroll
            for (int e = 0; e < 8; e++) accO[i][e] *= alpha[i];

        __syncthreads();

        // O += P V
        #pragma unroll 2
        for (int c = 0; c < 64; c++) {
            float pv[4];
            #pragma unroll
            for (int i = 0; i < 4; i++) pv[i] = sS[(tr * 4 + i) * 65 + c];
            #pragma unroll
            for (int e = 0; e < 8; e++) {
                const float vv = sV[c * 128 + tc + 16 * e];
                #pragma unroll
                for (int i = 0; i < 4; i++) accO[i][e] += pv[i] * vv;
            }
        }
    }

    // normalize + write [B, T, H*Dh]
    const int b = bh >> 4, h = bh & 15;
    #pragma unroll
    for (int i = 0; i < 4; i++) {
        const float inv = 1.f / l_i[i];
        const int t = q0 + tr * 4 + i;
        float* dst = O + ((size_t)(b * TT + t)) * NN + h * DHH;
        #pragma unroll
        for (int e = 0; e < 8; e++)
            dst[tc + 16 * e] = accO[i][e] * inv;
    }
}

// ---------------------------------------------------------------------------
extern "C" void kernel_launch(void* const* d_in, const int* in_sizes, int n_in,
                              void* d_out, int out_size)
{
    const float* x  = (const float*)d_in[0];
    const float* Wq = (const float*)d_in[1];
    const float* bq = (const float*)d_in[2];
    const float* Wk = (const float*)d_in[3];
    const float* bk = (const float*)d_in[4];
    const float* Wv = (const float*)d_in[5];
    const float* bv = (const float*)d_in[6];
    const float* Wp = (const float*)d_in[7];
    const float* bp = (const float*)d_in[8];
    float* out = (float*)d_out;

    float *q, *k, *v, *o;
    cudaGetSymbolAddress((void**)&q, g_q);
    cudaGetSymbolAddress((void**)&k, g_k);
    cudaGetSymbolAddress((void**)&v, g_v);
    cudaGetSymbolAddress((void**)&o, g_o);

    const int smem = (64 * 129 * 2 + 64 * 128 + 64 * 65) * sizeof(float);  // 115456
    cudaFuncSetAttribute(attn_kernel, cudaFuncAttributeMaxDynamicSharedMemorySize, smem);

    dim3 gg(NN / 128, MM / 128);   // (16, 32)
    gemm_kernel<<<gg, 256>>>(x, Wq, bq, q, 0);
    gemm_kernel<<<gg, 256>>>(x, Wk, bk, k, 0);
    gemm_kernel<<<gg, 256>>>(x, Wv, bv, v, 0);

    attn_kernel<<<dim3(TT / 64, BB * HH), 256, smem>>>(q, k, v, o);

    gemm_kernel<<<gg, 256>>>(o, Wp, bp, out, 1);
}

// round 2
// speedup vs baseline: 2.2913x; 2.2913x over previous
#include <cuda_runtime.h>
#include <math.h>
#include <stdint.h>

#define BB  2
#define TT  2048
#define DD  2048
#define HH  16
#define DHH 128
#define MM  (BB*TT)    // 4096
#define NN  (HH*DHH)   // 2048
#define KK  DD         // 2048

// Scratch (allocation-free rule: __device__ globals)
__device__ float g_q[(size_t)BB*HH*TT*DHH];
__device__ float g_k[(size_t)BB*HH*TT*DHH];
__device__ float g_v[(size_t)BB*HH*TT*DHH];
__device__ float g_o[(size_t)BB*TT*NN];

__device__ __forceinline__ uint32_t f2tf_u(float x) {
    uint32_t r;
    asm("cvt.rna.tf32.f32 %0, %1;" : "=r"(r) : "f"(x));
    return r;
}
__device__ __forceinline__ float f2tf(float x) {
    return __uint_as_float(f2tf_u(x));
}

#define MMA_TF32(c, a, b)                                                     \
    asm volatile(                                                             \
        "mma.sync.aligned.m16n8k8.row.col.f32.tf32.tf32.f32 "                 \
        "{%0,%1,%2,%3}, {%4,%5,%6,%7}, {%8,%9}, {%0,%1,%2,%3};"               \
        : "+f"((c)[0]), "+f"((c)[1]), "+f"((c)[2]), "+f"((c)[3])              \
        : "r"((a)[0]), "r"((a)[1]), "r"((a)[2]), "r"((a)[3]),                 \
          "r"((b)[0]), "r"((b)[1]))

// ---------------------------------------------------------------------------
// TF32 tensor-core GEMM: C = A(MxK) * W + bias
// mode 0: W is [H, D, Dh], output headed [B,H,T,Dh]; mode 1: W [K,N], C [M,N]
// BM=BN=128, BK=16, 256 threads (8 warps, 2x4), warp tile 64x32 (4x4 atoms).
// ---------------------------------------------------------------------------
__global__ __launch_bounds__(256) void gemm_tc(
    const float* __restrict__ A, const float* __restrict__ W,
    const float* __restrict__ bias, float* __restrict__ C, int mode)
{
    __shared__ float As[128][20];   // [row][k], pad to 20 -> conflict-free frags
    __shared__ float Bs[16][136];   // [k][n],  pad to 136 -> conflict-free frags

    const int bx = blockIdx.x, by = blockIdx.y, tid = threadIdx.x;
    const int wid = tid >> 5, lane = tid & 31;
    const int gid = lane >> 2, tig = lane & 3;
    const int wr = wid >> 2, wc = wid & 3;
    const int m0 = by * 128;

    const float* Aptr = A + (size_t)m0 * KK;
    const float* Bptr;
    int ldb;
    if (mode == 0) { Bptr = W + (size_t)bx * ((size_t)KK * 128); ldb = 128; }
    else           { Bptr = W + bx * 128;                        ldb = NN;  }

    // Global staging indices
    const int ar  = tid >> 1;          // A row 0..127
    const int ac  = (tid & 1) * 8;     // A k-col base (0 or 8)
    const int bkr = tid >> 4;          // B k-row 0..15
    const int bnc = (tid & 15) * 8;    // B n-col base

    float4 pa0, pa1, pb0, pb1;
    pa0 = *(const float4*)(Aptr + (size_t)ar * KK + ac);
    pa1 = *(const float4*)(Aptr + (size_t)ar * KK + ac + 4);
    pb0 = *(const float4*)(Bptr + (size_t)bkr * ldb + bnc);
    pb1 = *(const float4*)(Bptr + (size_t)bkr * ldb + bnc + 4);

    float acc[4][4][4];
    #pragma unroll
    for (int i = 0; i < 4; i++)
        #pragma unroll
        for (int j = 0; j < 4; j++)
            #pragma unroll
            for (int e = 0; e < 4; e++) acc[i][j][e] = 0.f;

    for (int k0 = 0; k0 < KK; k0 += 16) {
        __syncthreads();
        // stage (tf32-rounded) into smem
        As[ar][ac + 0] = f2tf(pa0.x); As[ar][ac + 1] = f2tf(pa0.y);
        As[ar][ac + 2] = f2tf(pa0.z); As[ar][ac + 3] = f2tf(pa0.w);
        As[ar][ac + 4] = f2tf(pa1.x); As[ar][ac + 5] = f2tf(pa1.y);
        As[ar][ac + 6] = f2tf(pa1.z); As[ar][ac + 7] = f2tf(pa1.w);
        float4 tb0, tb1;
        tb0.x = f2tf(pb0.x); tb0.y = f2tf(pb0.y); tb0.z = f2tf(pb0.z); tb0.w = f2tf(pb0.w);
        tb1.x = f2tf(pb1.x); tb1.y = f2tf(pb1.y); tb1.z = f2tf(pb1.z); tb1.w = f2tf(pb1.w);
        *(float4*)(&Bs[bkr][bnc])     = tb0;
        *(float4*)(&Bs[bkr][bnc + 4]) = tb1;
        __syncthreads();

        if (k0 + 16 < KK) {
            pa0 = *(const float4*)(Aptr + (size_t)ar * KK + k0 + 16 + ac);
            pa1 = *(const float4*)(Aptr + (size_t)ar * KK + k0 + 16 + ac + 4);
            pb0 = *(const float4*)(Bptr + (size_t)(k0 + 16 + bkr) * ldb + bnc);
            pb1 = *(const float4*)(Bptr + (size_t)(k0 + 16 + bkr) * ldb + bnc + 4);
        }

        #pragma unroll
        for (int ks = 0; ks < 16; ks += 8) {
            uint32_t af[4][4], bf[4][2];
            #pragma unroll
            for (int ma = 0; ma < 4; ma++) {
                const int r = wr * 64 + ma * 16 + gid;
                af[ma][0] = __float_as_uint(As[r][ks + tig]);
                af[ma][1] = __float_as_uint(As[r + 8][ks + tig]);
                af[ma][2] = __float_as_uint(As[r][ks + tig + 4]);
                af[ma][3] = __float_as_uint(As[r + 8][ks + tig + 4]);
            }
            #pragma unroll
            for (int na = 0; na < 4; na++) {
                const int n = wc * 32 + na * 8 + gid;
                bf[na][0] = __float_as_uint(Bs[ks + tig][n]);
                bf[na][1] = __float_as_uint(Bs[ks + tig + 4][n]);
            }
            #pragma unroll
            for (int ma = 0; ma < 4; ma++)
                #pragma unroll
                for (int na = 0; na < 4; na++)
                    MMA_TF32(acc[ma][na], af[ma], bf[na]);
        }
    }

    // Epilogue: bias + store
    #pragma unroll
    for (int ma = 0; ma < 4; ma++) {
        #pragma unroll
        for (int na = 0; na < 4; na++) {
            const int r  = m0 + wr * 64 + ma * 16 + gid;     // global m (row 0)
            const int nl = wc * 32 + na * 8 + 2 * tig;       // n within 128-tile
            const int ng = bx * 128 + nl;                    // global n
            const float b0 = bias[ng], b1 = bias[ng + 1];
            float* dst0;
            float* dst1;
            if (mode == 0) {
                const int bb0 = r >> 11,        t0 = r & (TT - 1);
                const int bb1 = (r + 8) >> 11,  t1 = (r + 8) & (TT - 1);
                dst0 = C + (((size_t)(bb0 * HH + bx)) * TT + t0) * DHH + nl;
                dst1 = C + (((size_t)(bb1 * HH + bx)) * TT + t1) * DHH + nl;
            } else {
                dst0 = C + (size_t)r * NN + ng;
                dst1 = C + (size_t)(r + 8) * NN + ng;
            }
            float2 v0, v1;
            v0.x = acc[ma][na][0] + b0; v0.y = acc[ma][na][1] + b1;
            v1.x = acc[ma][na][2] + b0; v1.y = acc[ma][na][3] + b1;
            *(float2*)dst0 = v0;
            *(float2*)dst1 = v1;
        }
    }
}

// ---------------------------------------------------------------------------
// Causal flash attention with tf32 tensor cores.
// Br=Bc=64, 128 threads (4 warps). Warp w owns S rows [w*16, w*16+16).
// S: 8 n-atoms (64 cols), K=128. PV: 16 n-atoms (Dh=128), K=64.
// ---------------------------------------------------------------------------
__global__ __launch_bounds__(128) void attn_tc(
    const float* __restrict__ Q, const float* __restrict__ Kg,
    const float* __restrict__ Vg, float* __restrict__ O)
{
    extern __shared__ float sh[];
    float* sQ  = sh;               // [64][132]
    float* sKV = sQ + 64 * 132;    // [64][136]  (K, later V)
    float* sS  = sKV + 64 * 136;   // [64][68]

    const int bh = blockIdx.y;
    const int q0 = blockIdx.x * 64;
    const int tid = threadIdx.x, wid = tid >> 5, lane = tid & 31;
    const int gid = lane >> 2, tig = lane & 3;
    const int wrow = wid * 16;
    const float scale = 0.08838834764831845f;   // 1/sqrt(128)

    const float* Qb = Q  + (size_t)bh * TT * DHH;
    const float* Kb = Kg + (size_t)bh * TT * DHH;
    const float* Vb = Vg + (size_t)bh * TT * DHH;

    // Load Q tile once (scaled + tf32-rounded)
    for (int i = tid; i < 64 * 32; i += 128) {
        const int r = i >> 5, c = (i & 31) * 4;
        float4 v = *(const float4*)(Qb + (size_t)(q0 + r) * DHH + c);
        sQ[r * 132 + c + 0] = f2tf(v.x * scale);
        sQ[r * 132 + c + 1] = f2tf(v.y * scale);
        sQ[r * 132 + c + 2] = f2tf(v.z * scale);
        sQ[r * 132 + c + 3] = f2tf(v.w * scale);
    }

    float accO[16][4];
    #pragma unroll
    for (int na = 0; na < 16; na++)
        #pragma unroll
        for (int e = 0; e < 4; e++) accO[na][e] = 0.f;
    float m_r[2] = {-INFINITY, -INFINITY};
    float l_r[2] = {0.f, 0.f};

    for (int j0 = 0; j0 <= q0; j0 += 64) {
        __syncthreads();   // prev PV reads of sKV/sS done; sQ ready (1st iter)

        // Load K tile (tf32)
        for (int i = tid; i < 64 * 32; i += 128) {
            const int r = i >> 5, c = (i & 31) * 4;
            float4 v = *(const float4*)(Kb + (size_t)(j0 + r) * DHH + c);
            sKV[r * 136 + c + 0] = f2tf(v.x);
            sKV[r * 136 + c + 1] = f2tf(v.y);
            sKV[r * 136 + c + 2] = f2tf(v.z);
            sKV[r * 136 + c + 3] = f2tf(v.w);
        }
        __syncthreads();

        // S = Q K^T
        float accS[8][4];
        #pragma unroll
        for (int na = 0; na < 8; na++)
            #pragma unroll
            for (int e = 0; e < 4; e++) accS[na][e] = 0.f;

        #pragma unroll
        for (int ks = 0; ks < 128; ks += 8) {
            uint32_t a[4];
            a[0] = __float_as_uint(sQ[(wrow + gid) * 132 + ks + tig]);
            a[1] = __float_as_uint(sQ[(wrow + gid + 8) * 132 + ks + tig]);
            a[2] = __float_as_uint(sQ[(wrow + gid) * 132 + ks + tig + 4]);
            a[3] = __float_as_uint(sQ[(wrow + gid + 8) * 132 + ks + tig + 4]);
            #pragma unroll
            for (int na = 0; na < 8; na++) {
                uint32_t b[2];
                b[0] = __float_as_uint(sKV[(na * 8 + gid) * 136 + ks + tig]);
                b[1] = __float_as_uint(sKV[(na * 8 + gid) * 136 + ks + tig + 4]);
                MMA_TF32(accS[na], a, b);
            }
        }

        // Causal mask (diagonal tile only)
        if (j0 == q0) {
            const int qi0 = q0 + wrow + gid;
            const int qi1 = qi0 + 8;
            #pragma unroll
            for (int na = 0; na < 8; na++) {
                const int c0 = j0 + na * 8 + 2 * tig;
                if (c0 > qi0)     accS[na][0] = -INFINITY;
                if (c0 + 1 > qi0) accS[na][1] = -INFINITY;
                if (c0 > qi1)     accS[na][2] = -INFINITY;
                if (c0 + 1 > qi1) accS[na][3] = -INFINITY;
            }
        }

        // Online softmax for 2 rows per thread
        float alpha[2];
        #pragma unroll
        for (int rr = 0; rr < 2; rr++) {
            float mt = -INFINITY;
            #pragma unroll
            for (int na = 0; na < 8; na++)
                mt = fmaxf(mt, fmaxf(accS[na][2 * rr], accS[na][2 * rr + 1]));
            mt = fmaxf(mt, __shfl_xor_sync(0xffffffffu, mt, 1));
            mt = fmaxf(mt, __shfl_xor_sync(0xffffffffu, mt, 2));
            const float mn = fmaxf(m_r[rr], mt);
            alpha[rr] = __expf(m_r[rr] - mn);
            m_r[rr] = mn;
            float ls = 0.f;
            #pragma unroll
            for (int na = 0; na < 8; na++) {
                float p0 = __expf(accS[na][2 * rr] - mn);
                float p1 = __expf(accS[na][2 * rr + 1] - mn);
                accS[na][2 * rr] = p0;
                accS[na][2 * rr + 1] = p1;
                ls += p0 + p1;
            }
            ls += __shfl_xor_sync(0xffffffffu, ls, 1);
            ls += __shfl_xor_sync(0xffffffffu, ls, 2);
            l_r[rr] = l_r[rr] * alpha[rr] + ls;
        }

        // Store P (tf32) to sS
        #pragma unroll
        for (int na = 0; na < 8; na++) {
            const int cc = na * 8 + 2 * tig;
            sS[(wrow + gid) * 68 + cc]     = f2tf(accS[na][0]);
            sS[(wrow + gid) * 68 + cc + 1] = f2tf(accS[na][1]);
            sS[(wrow + gid + 8) * 68 + cc]     = f2tf(accS[na][2]);
            sS[(wrow + gid + 8) * 68 + cc + 1] = f2tf(accS[na][3]);
        }

        // Rescale O accumulators
        #pragma unroll
        for (int na = 0; na < 16; na++) {
            accO[na][0] *= alpha[0]; accO[na][1] *= alpha[0];
            accO[na][2] *= alpha[1]; accO[na][3] *= alpha[1];
        }

        __syncthreads();   // K reads complete, P visible

        // Load V tile (tf32) over K's buffer
        for (int i = tid; i < 64 * 32; i += 128) {
            const int r = i >> 5, c = (i & 31) * 4;
            float4 v = *(const float4*)(Vb + (size_t)(j0 + r) * DHH + c);
            sKV[r * 136 + c + 0] = f2tf(v.x);
            sKV[r * 136 + c + 1] = f2tf(v.y);
            sKV[r * 136 + c + 2] = f2tf(v.z);
            sKV[r * 136 + c + 3] = f2tf(v.w);
        }
        __syncthreads();

        // O += P V
        #pragma unroll
        for (int ks = 0; ks < 64; ks += 8) {
            uint32_t a[4];
            a[0] = __float_as_uint(sS[(wrow + gid) * 68 + ks + tig]);
            a[1] = __float_as_uint(sS[(wrow + gid + 8) * 68 + ks + tig]);
            a[2] = __float_as_uint(sS[(wrow + gid) * 68 + ks + tig + 4]);
            a[3] = __float_as_uint(sS[(wrow + gid + 8) * 68 + ks + tig + 4]);
            #pragma unroll
            for (int na = 0; na < 16; na++) {
                uint32_t b[2];
                b[0] = __float_as_uint(sKV[(ks + tig) * 136 + na * 8 + gid]);
                b[1] = __float_as_uint(sKV[(ks + tig + 4) * 136 + na * 8 + gid]);
                MMA_TF32(accO[na], a, b);
            }
        }
    }

    // Normalize + write [B, T, H*Dh]
    const int b = bh >> 4, h = bh & 15;
    const float inv0 = 1.f / l_r[0];
    const float inv1 = 1.f / l_r[1];
    const int t0 = q0 + wrow + gid;
    const int t1 = t0 + 8;
    float* base0 = O + ((size_t)(b * TT + t0)) * NN + h * DHH;
    float* base1 = O + ((size_t)(b * TT + t1)) * NN + h * DHH;
    #pragma unroll
    for (int na = 0; na < 16; na++) {
        const int cc = na * 8 + 2 * tig;
        float2 v0, v1;
        v0.x = accO[na][0] * inv0; v0.y = accO[na][1] * inv0;
        v1.x = accO[na][2] * inv1; v1.y = accO[na][3] * inv1;
        *(float2*)(base0 + cc) = v0;
        *(float2*)(base1 + cc) = v1;
    }
}

// ---------------------------------------------------------------------------
extern "C" void kernel_launch(void* const* d_in, const int* in_sizes, int n_in,
                              void* d_out, int out_size)
{
    const float* x  = (const float*)d_in[0];
    const float* Wq = (const float*)d_in[1];
    const float* bq = (const float*)d_in[2];
    const float* Wk = (const float*)d_in[3];
    const float* bk = (const float*)d_in[4];
    const float* Wv = (const float*)d_in[5];
    const float* bv = (const float*)d_in[6];
    const float* Wp = (const float*)d_in[7];
    const float* bp = (const float*)d_in[8];
    float* out = (float*)d_out;

    float *q, *k, *v, *o;
    cudaGetSymbolAddress((void**)&q, g_q);
    cudaGetSymbolAddress((void**)&k, g_k);
    cudaGetSymbolAddress((void**)&v, g_v);
    cudaGetSymbolAddress((void**)&o, g_o);

    const int smem = (64 * 132 + 64 * 136 + 64 * 68) * sizeof(float);  // 86016
    cudaFuncSetAttribute(attn_tc, cudaFuncAttributeMaxDynamicSharedMemorySize, smem);

    dim3 gg(NN / 128, MM / 128);   // (16, 32)
    gemm_tc<<<gg, 256>>>(x, Wq, bq, q, 0);
    gemm_tc<<<gg, 256>>>(x, Wk, bk, k, 0);
    gemm_tc<<<gg, 256>>>(x, Wv, bv, v, 0);

    attn_tc<<<dim3(TT / 64, BB * HH), 128, smem>>>(q, k, v, o);

    gemm_tc<<<gg, 256>>>(o, Wp, bp, out, 1);
}

// round 3
// speedup vs baseline: 3.1296x; 1.3659x over previous
#include <cuda_runtime.h>
#include <math.h>
#include <stdint.h>

#define BB  2
#define TT  2048
#define DD  2048
#define HH  16
#define DHH 128
#define MM  (BB*TT)    // 4096
#define NN  (HH*DHH)   // 2048
#define KK  DD         // 2048

// Scratch (allocation-free rule: __device__ globals)
__device__ float g_q[(size_t)BB*HH*TT*DHH];
__device__ float g_k[(size_t)BB*HH*TT*DHH];
__device__ float g_v[(size_t)BB*HH*TT*DHH];
__device__ float g_o[(size_t)BB*TT*NN];

__device__ __forceinline__ uint32_t f2tf_u(float x) {
    uint32_t r;
    asm("cvt.rna.tf32.f32 %0, %1;" : "=r"(r) : "f"(x));
    return r;
}
__device__ __forceinline__ float f2tf(float x) {
    return __uint_as_float(f2tf_u(x));
}

#define MMA_TF32(c, a, b)                                                     \
    asm volatile(                                                             \
        "mma.sync.aligned.m16n8k8.row.col.f32.tf32.tf32.f32 "                 \
        "{%0,%1,%2,%3}, {%4,%5,%6,%7}, {%8,%9}, {%0,%1,%2,%3};"               \
        : "+f"((c)[0]), "+f"((c)[1]), "+f"((c)[2]), "+f"((c)[3])              \
        : "r"((a)[0]), "r"((a)[1]), "r"((a)[2]), "r"((a)[3]),                 \
          "r"((b)[0]), "r"((b)[1]))

__device__ __forceinline__ uint32_t smem_u32(const void* p) {
    return (uint32_t)__cvta_generic_to_shared(p);
}
#define CP_ASYNC16(dst_u32, src)                                              \
    asm volatile("cp.async.cg.shared.global [%0], [%1], 16;"                  \
                 :: "r"(dst_u32), "l"(src))
#define CP_COMMIT() asm volatile("cp.async.commit_group;")
#define CP_WAIT(n)  asm volatile("cp.async.wait_group %0;" :: "n"(n))

// ---------------------------------------------------------------------------
// TF32 tensor-core GEMM, cp.async double-buffered.
// mode 0: W is [H, D, Dh], output headed [B,H,T,Dh]; mode 1: W [K,N], C [M,N]
// BM=BN=128, BK=16, 256 threads (8 warps 2x4), warp tile 64x32.
// ---------------------------------------------------------------------------
__global__ __launch_bounds__(256, 2) void gemm_tc(
    const float* __restrict__ A, const float* __restrict__ W,
    const float* __restrict__ bias, float* __restrict__ C, int mode)
{
    __shared__ float As[2][128][20];   // raw fp32, pad 20 (80B, 16B-aligned)
    __shared__ float Bs[2][16][136];   // raw fp32, pad 136

    const int bx = blockIdx.x, by = blockIdx.y, tid = threadIdx.x;
    const int wid = tid >> 5, lane = tid & 31;
    const int gid = lane >> 2, tig = lane & 3;
    const int wr = wid >> 2, wc = wid & 3;
    const int m0 = by * 128;

    const float* Aptr = A + (size_t)m0 * KK;
    const float* Bptr;
    int ldb;
    if (mode == 0) { Bptr = W + (size_t)bx * ((size_t)KK * 128); ldb = 128; }
    else           { Bptr = W + bx * 128;                        ldb = NN;  }

    const int ar  = tid >> 1;          // A row 0..127
    const int ac  = (tid & 1) * 8;     // A k-col base
    const int bkr = tid >> 4;          // B k-row 0..15
    const int bnc = (tid & 15) * 8;    // B n-col base

    // stage loader
    auto load_stage = [&](int s, int k0) {
        uint32_t da0 = smem_u32(&As[s][ar][ac]);
        uint32_t da1 = smem_u32(&As[s][ar][ac + 4]);
        CP_ASYNC16(da0, Aptr + (size_t)ar * KK + k0 + ac);
        CP_ASYNC16(da1, Aptr + (size_t)ar * KK + k0 + ac + 4);
        uint32_t db0 = smem_u32(&Bs[s][bkr][bnc]);
        uint32_t db1 = smem_u32(&Bs[s][bkr][bnc + 4]);
        CP_ASYNC16(db0, Bptr + (size_t)(k0 + bkr) * ldb + bnc);
        CP_ASYNC16(db1, Bptr + (size_t)(k0 + bkr) * ldb + bnc + 4);
    };

    float acc[4][4][4];
    #pragma unroll
    for (int i = 0; i < 4; i++)
        #pragma unroll
        for (int j = 0; j < 4; j++)
            #pragma unroll
            for (int e = 0; e < 4; e++) acc[i][j][e] = 0.f;

    load_stage(0, 0);  CP_COMMIT();
    load_stage(1, 16); CP_COMMIT();
    CP_WAIT(1);
    __syncthreads();

    int cur = 0;
    for (int k0 = 0; k0 < KK; k0 += 16) {
        // compute on stage cur
        #pragma unroll
        for (int ks = 0; ks < 16; ks += 8) {
            uint32_t af[4][4], bf[4][2];
            #pragma unroll
            for (int ma = 0; ma < 4; ma++) {
                const int r = wr * 64 + ma * 16 + gid;
                af[ma][0] = f2tf_u(As[cur][r][ks + tig]);
                af[ma][1] = f2tf_u(As[cur][r + 8][ks + tig]);
                af[ma][2] = f2tf_u(As[cur][r][ks + tig + 4]);
                af[ma][3] = f2tf_u(As[cur][r + 8][ks + tig + 4]);
            }
            #pragma unroll
            for (int na = 0; na < 4; na++) {
                const int n = wc * 32 + na * 8 + gid;
                bf[na][0] = f2tf_u(Bs[cur][ks + tig][n]);
                bf[na][1] = f2tf_u(Bs[cur][ks + tig + 4][n]);
            }
            #pragma unroll
            for (int ma = 0; ma < 4; ma++)
                #pragma unroll
                for (int na = 0; na < 4; na++)
                    MMA_TF32(acc[ma][na], af[ma], bf[na]);
        }
        __syncthreads();                    // all reads of cur done
        if (k0 + 32 < KK) load_stage(cur, k0 + 32);
        CP_COMMIT();
        CP_WAIT(1);                         // other stage ready
        __syncthreads();
        cur ^= 1;
    }

    // Epilogue: bias + store
    #pragma unroll
    for (int ma = 0; ma < 4; ma++) {
        #pragma unroll
        for (int na = 0; na < 4; na++) {
            const int r  = m0 + wr * 64 + ma * 16 + gid;
            const int nl = wc * 32 + na * 8 + 2 * tig;
            const int ng = bx * 128 + nl;
            const float b0 = bias[ng], b1 = bias[ng + 1];
            float* dst0;
            float* dst1;
            if (mode == 0) {
                const int bb0 = r >> 11,       t0 = r & (TT - 1);
                const int bb1 = (r + 8) >> 11, t1 = (r + 8) & (TT - 1);
                dst0 = C + (((size_t)(bb0 * HH + bx)) * TT + t0) * DHH + nl;
                dst1 = C + (((size_t)(bb1 * HH + bx)) * TT + t1) * DHH + nl;
            } else {
                dst0 = C + (size_t)r * NN + ng;
                dst1 = C + (size_t)(r + 8) * NN + ng;
            }
            float2 v0, v1;
            v0.x = acc[ma][na][0] + b0; v0.y = acc[ma][na][1] + b1;
            v1.x = acc[ma][na][2] + b0; v1.y = acc[ma][na][3] + b1;
            *(float2*)dst0 = v0;
            *(float2*)dst1 = v1;
        }
    }
}

// ---------------------------------------------------------------------------
// Causal flash attention, tf32 tensor cores, 8 warps, cp.async pipelined K/V.
// Br=Bc=64. Warp (wr,wc): rows wr*16..+16; S cols wc*32..+32; O cols wc*64..+64.
// Softmax: row-parallel pass, 4 threads per row, stats in smem.
// ---------------------------------------------------------------------------
#define LDQ 132
#define LDK 132
#define LDV 136
#define LDSS 68

__global__ __launch_bounds__(256) void attn_tc(
    const float* __restrict__ Q, const float* __restrict__ Kg,
    const float* __restrict__ Vg, float* __restrict__ O)
{
    extern __shared__ float sh[];
    float* sQ = sh;                 // [64][132] tf32 (scaled)
    float* sK = sQ + 64 * LDQ;      // [64][132] raw -> tf32 in place
    float* sV = sK + 64 * LDK;      // [64][136] raw -> tf32 in place
    float* sS = sV + 64 * LDV;      // [64][68]  S then P
    float* sM = sS + 64 * LDSS;     // [64]
    float* sL = sM + 64;            // [64]
    float* sA = sL + 64;            // [64]

    const int bh = blockIdx.y;
    const int q0 = blockIdx.x * 64;
    const int tid = threadIdx.x, wid = tid >> 5, lane = tid & 31;
    const int gid = lane >> 2, tig = lane & 3;
    const int wr = wid >> 1, wc = wid & 1;
    const int wrow = wr * 16;
    const float scale = 0.08838834764831845f;  // 1/sqrt(128)

    const float* Qb = Q  + (size_t)bh * TT * DHH;
    const float* Kb = Kg + (size_t)bh * TT * DHH;
    const float* Vb = Vg + (size_t)bh * TT * DHH;

    // init stats
    if (tid < 64) { sM[tid] = -INFINITY; sL[tid] = 0.f; }

    // issue K_0 (raw, async)
    #pragma unroll
    for (int ch = 0; ch < 8; ch++) {
        const int i = tid + ch * 256;
        const int r = i >> 5, c4 = (i & 31) * 4;
        CP_ASYNC16(smem_u32(sK + r * LDK + c4), Kb + (size_t)r * DHH + c4);
    }
    CP_COMMIT();

    // load Q (scaled + tf32) synchronously
    #pragma unroll
    for (int ch = 0; ch < 8; ch++) {
        const int i = tid + ch * 256;
        const int r = i >> 5, c4 = (i & 31) * 4;
        float4 v = *(const float4*)(Qb + (size_t)(q0 + r) * DHH + c4);
        sQ[r * LDQ + c4 + 0] = f2tf(v.x * scale);
        sQ[r * LDQ + c4 + 1] = f2tf(v.y * scale);
        sQ[r * LDQ + c4 + 2] = f2tf(v.z * scale);
        sQ[r * LDQ + c4 + 3] = f2tf(v.w * scale);
    }

    float accO[8][4];
    #pragma unroll
    for (int na = 0; na < 8; na++)
        #pragma unroll
        for (int e = 0; e < 4; e++) accO[na][e] = 0.f;

    const int nj = (q0 >> 6) + 1;
    for (int j = 0; j < nj; j++) {
        const int j0 = j * 64;
        __syncthreads();   // PV_{j-1} done with sV/sS; Q/stats ready (j=0)

        // issue V_j (raw, async)
        #pragma unroll
        for (int ch = 0; ch < 8; ch++) {
            const int i = tid + ch * 256;
            const int r = i >> 5, c4 = (i & 31) * 4;
            CP_ASYNC16(smem_u32(sV + r * LDV + c4),
                       Vb + (size_t)(j0 + r) * DHH + c4);
        }
        CP_COMMIT();

        CP_WAIT(1);        // K_j arrived
        __syncthreads();

        // convert K in place (raw -> tf32)
        #pragma unroll
        for (int ch = 0; ch < 8; ch++) {
            const int i = tid + ch * 256;
            const int r = i >> 5, c4 = (i & 31) * 4;
            float4 t = *(float4*)(sK + r * LDK + c4);
            t.x = f2tf(t.x); t.y = f2tf(t.y); t.z = f2tf(t.z); t.w = f2tf(t.w);
            *(float4*)(sK + r * LDK + c4) = t;
        }
        __syncthreads();

        // S = Q K^T  (4 n-atoms per warp: cols wc*32 + na*8)
        float accS[4][4];
        #pragma unroll
        for (int na = 0; na < 4; na++)
            #pragma unroll
            for (int e = 0; e < 4; e++) accS[na][e] = 0.f;

        #pragma unroll
        for (int ks = 0; ks < 128; ks += 8) {
            uint32_t a[4];
            a[0] = __float_as_uint(sQ[(wrow + gid) * LDQ + ks + tig]);
            a[1] = __float_as_uint(sQ[(wrow + gid + 8) * LDQ + ks + tig]);
            a[2] = __float_as_uint(sQ[(wrow + gid) * LDQ + ks + tig + 4]);
            a[3] = __float_as_uint(sQ[(wrow + gid + 8) * LDQ + ks + tig + 4]);
            #pragma unroll
            for (int na = 0; na < 4; na++) {
                const int n = wc * 32 + na * 8 + gid;
                uint32_t b[2];
                b[0] = __float_as_uint(sK[n * LDK + ks + tig]);
                b[1] = __float_as_uint(sK[n * LDK + ks + tig + 4]);
                MMA_TF32(accS[na], a, b);
            }
        }

        // causal mask (diagonal tile only)
        if (j0 == q0) {
            const int qi0 = q0 + wrow + gid;
            const int qi1 = qi0 + 8;
            #pragma unroll
            for (int na = 0; na < 4; na++) {
                const int c0 = j0 + wc * 32 + na * 8 + 2 * tig;
                if (c0 > qi0)     accS[na][0] = -INFINITY;
                if (c0 + 1 > qi0) accS[na][1] = -INFINITY;
                if (c0 > qi1)     accS[na][2] = -INFINITY;
                if (c0 + 1 > qi1) accS[na][3] = -INFINITY;
            }
        }

        // write raw S to smem
        #pragma unroll
        for (int na = 0; na < 4; na++) {
            const int cc = wc * 32 + na * 8 + 2 * tig;
            sS[(wrow + gid) * LDSS + cc]         = accS[na][0];
            sS[(wrow + gid) * LDSS + cc + 1]     = accS[na][1];
            sS[(wrow + gid + 8) * LDSS + cc]     = accS[na][2];
            sS[(wrow + gid + 8) * LDSS + cc + 1] = accS[na][3];
        }

        CP_WAIT(0);        // V_j arrived
        __syncthreads();   // S visible everywhere; K reads done

        // issue K_{j+1}
        if (j + 1 < nj) {
            #pragma unroll
            for (int ch = 0; ch < 8; ch++) {
                const int i = tid + ch * 256;
                const int r = i >> 5, c4 = (i & 31) * 4;
                CP_ASYNC16(smem_u32(sK + r * LDK + c4),
                           Kb + (size_t)(j0 + 64 + r) * DHH + c4);
            }
        }
        CP_COMMIT();

        // row-parallel online softmax (4 threads per row)
        {
            const int row = tid >> 2, qq = tid & 3;
            float* rowp = sS + row * LDSS + qq * 16;
            float4 v0 = *(float4*)(rowp);
            float4 v1 = *(float4*)(rowp + 4);
            float4 v2 = *(float4*)(rowp + 8);
            float4 v3 = *(float4*)(rowp + 12);
            float mt = fmaxf(fmaxf(fmaxf(v0.x, v0.y), fmaxf(v0.z, v0.w)),
                             fmaxf(fmaxf(v1.x, v1.y), fmaxf(v1.z, v1.w)));
            mt = fmaxf(mt, fmaxf(fmaxf(fmaxf(v2.x, v2.y), fmaxf(v2.z, v2.w)),
                                 fmaxf(fmaxf(v3.x, v3.y), fmaxf(v3.z, v3.w))));
            mt = fmaxf(mt, __shfl_xor_sync(0xffffffffu, mt, 1));
            mt = fmaxf(mt, __shfl_xor_sync(0xffffffffu, mt, 2));
            const float mo = sM[row];
            const float mn = fmaxf(mo, mt);
            const float alpha = __expf(mo - mn);
            v0.x = __expf(v0.x - mn); v0.y = __expf(v0.y - mn);
            v0.z = __expf(v0.z - mn); v0.w = __expf(v0.w - mn);
            v1.x = __expf(v1.x - mn); v1.y = __expf(v1.y - mn);
            v1.z = __expf(v1.z - mn); v1.w = __expf(v1.w - mn);
            v2.x = __expf(v2.x - mn); v2.y = __expf(v2.y - mn);
            v2.z = __expf(v2.z - mn); v2.w = __expf(v2.w - mn);
            v3.x = __expf(v3.x - mn); v3.y = __expf(v3.y - mn);
            v3.z = __expf(v3.z - mn); v3.w = __expf(v3.w - mn);
            float ls = (v0.x + v0.y + v0.z + v0.w) + (v1.x + v1.y + v1.z + v1.w)
                     + (v2.x + v2.y + v2.z + v2.w) + (v3.x + v3.y + v3.z + v3.w);
            ls += __shfl_xor_sync(0xffffffffu, ls, 1);
            ls += __shfl_xor_sync(0xffffffffu, ls, 2);
            // write P (tf32-rounded)
            v0.x = f2tf(v0.x); v0.y = f2tf(v0.y); v0.z = f2tf(v0.z); v0.w = f2tf(v0.w);
            v1.x = f2tf(v1.x); v1.y = f2tf(v1.y); v1.z = f2tf(v1.z); v1.w = f2tf(v1.w);
            v2.x = f2tf(v2.x); v2.y = f2tf(v2.y); v2.z = f2tf(v2.z); v2.w = f2tf(v2.w);
            v3.x = f2tf(v3.x); v3.y = f2tf(v3.y); v3.z = f2tf(v3.z); v3.w = f2tf(v3.w);
            *(float4*)(rowp)      = v0;
            *(float4*)(rowp + 4)  = v1;
            *(float4*)(rowp + 8)  = v2;
            *(float4*)(rowp + 12) = v3;
            if (qq == 0) {
                sM[row] = mn;
                sL[row] = sL[row] * alpha + ls;
                sA[row] = alpha;
            }
        }

        // convert V in place (raw -> tf32)
        #pragma unroll
        for (int ch = 0; ch < 8; ch++) {
            const int i = tid + ch * 256;
            const int r = i >> 5, c4 = (i & 31) * 4;
            float4 t = *(float4*)(sV + r * LDV + c4);
            t.x = f2tf(t.x); t.y = f2tf(t.y); t.z = f2tf(t.z); t.w = f2tf(t.w);
            *(float4*)(sV + r * LDV + c4) = t;
        }
        __syncthreads();

        // rescale accO
        const float al0 = sA[wrow + gid];
        const float al1 = sA[wrow + gid + 8];
        #pragma unroll
        for (int na = 0; na < 8; na++) {
            accO[na][0] *= al0; accO[na][1] *= al0;
            accO[na][2] *= al1; accO[na][3] *= al1;
        }

        // O += P V   (8 n-atoms per warp: cols wc*64 + na*8)
        #pragma unroll
        for (int ks = 0; ks < 64; ks += 8) {
            uint32_t a[4];
            a[0] = __float_as_uint(sS[(wrow + gid) * LDSS + ks + tig]);
            a[1] = __float_as_uint(sS[(wrow + gid + 8) * LDSS + ks + tig]);
            a[2] = __float_as_uint(sS[(wrow + gid) * LDSS + ks + tig + 4]);
            a[3] = __float_as_uint(sS[(wrow + gid + 8) * LDSS + ks + tig + 4]);
            #pragma unroll
            for (int na = 0; na < 8; na++) {
                const int n = wc * 64 + na * 8 + gid;
                uint32_t b[2];
                b[0] = __float_as_uint(sV[(ks + tig) * LDV + n]);
                b[1] = __float_as_uint(sV[(ks + tig + 4) * LDV + n]);
                MMA_TF32(accO[na], a, b);
            }
        }
    }

    // normalize + write [B, T, H*Dh]
    const int b = bh >> 4, h = bh & 15;
    const int lr = wrow + gid;
    const float inv0 = 1.f / sL[lr];
    const float inv1 = 1.f / sL[lr + 8];
    const int t0 = q0 + lr;
    float* base0 = O + ((size_t)(b * TT + t0)) * NN + h * DHH;
    float* base1 = O + ((size_t)(b * TT + t0 + 8)) * NN + h * DHH;
    #pragma unroll
    for (int na = 0; na < 8; na++) {
        const int cc = wc * 64 + na * 8 + 2 * tig;
        float2 v0, v1;
        v0.x = accO[na][0] * inv0; v0.y = accO[na][1] * inv0;
        v1.x = accO[na][2] * inv1; v1.y = accO[na][3] * inv1;
        *(float2*)(base0 + cc) = v0;
        *(float2*)(base1 + cc) = v1;
    }
}

// ---------------------------------------------------------------------------
extern "C" void kernel_launch(void* const* d_in, const int* in_sizes, int n_in,
                              void* d_out, int out_size)
{
    const float* x  = (const float*)d_in[0];
    const float* Wq = (const float*)d_in[1];
    const float* bq = (const float*)d_in[2];
    const float* Wk = (const float*)d_in[3];
    const float* bk = (const float*)d_in[4];
    const float* Wv = (const float*)d_in[5];
    const float* bv = (const float*)d_in[6];
    const float* Wp = (const float*)d_in[7];
    const float* bp = (const float*)d_in[8];
    float* out = (float*)d_out;

    float *q, *k, *v, *o;
    cudaGetSymbolAddress((void**)&q, g_q);
    cudaGetSymbolAddress((void**)&k, g_k);
    cudaGetSymbolAddress((void**)&v, g_v);
    cudaGetSymbolAddress((void**)&o, g_o);

    const int smem = (64 * LDQ + 64 * LDK + 64 * LDV + 64 * LDSS + 192) * sizeof(float);
    cudaFuncSetAttribute(attn_tc, cudaFuncAttributeMaxDynamicSharedMemorySize, smem);

    dim3 gg(NN / 128, MM / 128);   // (16, 32)
    gemm_tc<<<gg, 256>>>(x, Wq, bq, q, 0);
    gemm_tc<<<gg, 256>>>(x, Wk, bk, k, 0);
    gemm_tc<<<gg, 256>>>(x, Wv, bv, v, 0);

    attn_tc<<<dim3(TT / 64, BB * HH), 256, smem>>>(q, k, v, o);

    gemm_tc<<<gg, 256>>>(o, Wp, bp, out, 1);
}

// round 4
// speedup vs baseline: 3.4628x; 1.1065x over previous
#include <cuda_runtime.h>
#include <math.h>
#include <stdint.h>

#define BB  2
#define TT  2048
#define DD  2048
#define HH  16
#define DHH 128
#define MM  (BB*TT)    // 4096
#define NN  (HH*DHH)   // 2048
#define KK  DD         // 2048

// Scratch (allocation-free rule: __device__ globals)
__device__ float g_q[(size_t)BB*HH*TT*DHH];
__device__ float g_k[(size_t)BB*HH*TT*DHH];
__device__ float g_v[(size_t)BB*HH*TT*DHH];
__device__ float g_o[(size_t)BB*TT*NN];

__device__ __forceinline__ uint32_t f2tf_u(float x) {
    uint32_t r;
    asm("cvt.rna.tf32.f32 %0, %1;" : "=r"(r) : "f"(x));
    return r;
}
__device__ __forceinline__ float f2tf(float x) {
    return __uint_as_float(f2tf_u(x));
}

#define MMA_TF32(c, a, b)                                                     \
    asm volatile(                                                             \
        "mma.sync.aligned.m16n8k8.row.col.f32.tf32.tf32.f32 "                 \
        "{%0,%1,%2,%3}, {%4,%5,%6,%7}, {%8,%9}, {%0,%1,%2,%3};"               \
        : "+f"((c)[0]), "+f"((c)[1]), "+f"((c)[2]), "+f"((c)[3])              \
        : "r"((a)[0]), "r"((a)[1]), "r"((a)[2]), "r"((a)[3]),                 \
          "r"((b)[0]), "r"((b)[1]))

__device__ __forceinline__ uint32_t smem_u32(const void* p) {
    return (uint32_t)__cvta_generic_to_shared(p);
}
#define CP_ASYNC16(dst_u32, src)                                              \
    asm volatile("cp.async.cg.shared.global [%0], [%1], 16;"                  \
                 :: "r"(dst_u32), "l"(src))
#define CP_COMMIT() asm volatile("cp.async.commit_group;")
#define CP_WAIT(n)  asm volatile("cp.async.wait_group %0;" :: "n"(n))

// ---------------------------------------------------------------------------
// Fused QKV TF32 GEMM, cp.async double-buffered.
// blockIdx.z selects (Wq,bq)->q, (Wk,bk)->k, (Wv,bv)->v. W is [H, D, Dh].
// Output headed [B,H,T,Dh]. BM=BN=128, BK=16, 256 threads, warp tile 64x32.
// ---------------------------------------------------------------------------
__global__ __launch_bounds__(256, 2) void gemm_qkv(
    const float* __restrict__ A,
    const float* __restrict__ Wq, const float* __restrict__ bq,
    const float* __restrict__ Wk, const float* __restrict__ bk,
    const float* __restrict__ Wv, const float* __restrict__ bv,
    float* __restrict__ Cq, float* __restrict__ Ck, float* __restrict__ Cv)
{
    __shared__ float As[2][128][20];
    __shared__ float Bs[2][16][136];

    const int bx = blockIdx.x, by = blockIdx.y, bz = blockIdx.z;
    const int tid = threadIdx.x;
    const int wid = tid >> 5, lane = tid & 31;
    const int gid = lane >> 2, tig = lane & 3;
    const int wr = wid >> 2, wc = wid & 3;
    const int m0 = by * 128;

    const float* W    = (bz == 0) ? Wq : (bz == 1) ? Wk : Wv;
    const float* bias = (bz == 0) ? bq : (bz == 1) ? bk : bv;
    float* C          = (bz == 0) ? Cq : (bz == 1) ? Ck : Cv;

    const float* Aptr = A + (size_t)m0 * KK;
    const float* Bptr = W + (size_t)bx * ((size_t)KK * 128);

    const int ar  = tid >> 1;
    const int ac  = (tid & 1) * 8;
    const int bkr = tid >> 4;
    const int bnc = (tid & 15) * 8;

    auto load_stage = [&](int s, int k0) {
        CP_ASYNC16(smem_u32(&As[s][ar][ac]),     Aptr + (size_t)ar * KK + k0 + ac);
        CP_ASYNC16(smem_u32(&As[s][ar][ac + 4]), Aptr + (size_t)ar * KK + k0 + ac + 4);
        CP_ASYNC16(smem_u32(&Bs[s][bkr][bnc]),     Bptr + (size_t)(k0 + bkr) * 128 + bnc);
        CP_ASYNC16(smem_u32(&Bs[s][bkr][bnc + 4]), Bptr + (size_t)(k0 + bkr) * 128 + bnc + 4);
    };

    float acc[4][4][4];
    #pragma unroll
    for (int i = 0; i < 4; i++)
        #pragma unroll
        for (int j = 0; j < 4; j++)
            #pragma unroll
            for (int e = 0; e < 4; e++) acc[i][j][e] = 0.f;

    load_stage(0, 0);  CP_COMMIT();
    load_stage(1, 16); CP_COMMIT();
    CP_WAIT(1);
    __syncthreads();

    int cur = 0;
    for (int k0 = 0; k0 < KK; k0 += 16) {
        #pragma unroll
        for (int ks = 0; ks < 16; ks += 8) {
            uint32_t af[4][4], bf[4][2];
            #pragma unroll
            for (int ma = 0; ma < 4; ma++) {
                const int r = wr * 64 + ma * 16 + gid;
                af[ma][0] = f2tf_u(As[cur][r][ks + tig]);
                af[ma][1] = f2tf_u(As[cur][r + 8][ks + tig]);
                af[ma][2] = f2tf_u(As[cur][r][ks + tig + 4]);
                af[ma][3] = f2tf_u(As[cur][r + 8][ks + tig + 4]);
            }
            #pragma unroll
            for (int na = 0; na < 4; na++) {
                const int n = wc * 32 + na * 8 + gid;
                bf[na][0] = f2tf_u(Bs[cur][ks + tig][n]);
                bf[na][1] = f2tf_u(Bs[cur][ks + tig + 4][n]);
            }
            #pragma unroll
            for (int ma = 0; ma < 4; ma++)
                #pragma unroll
                for (int na = 0; na < 4; na++)
                    MMA_TF32(acc[ma][na], af[ma], bf[na]);
        }
        __syncthreads();
        if (k0 + 32 < KK) load_stage(cur, k0 + 32);
        CP_COMMIT();
        CP_WAIT(1);
        __syncthreads();
        cur ^= 1;
    }

    #pragma unroll
    for (int ma = 0; ma < 4; ma++) {
        #pragma unroll
        for (int na = 0; na < 4; na++) {
            const int r  = m0 + wr * 64 + ma * 16 + gid;
            const int nl = wc * 32 + na * 8 + 2 * tig;
            const int ng = bx * 128 + nl;
            const float b0 = bias[ng], b1 = bias[ng + 1];
            const int bb0 = r >> 11,       t0 = r & (TT - 1);
            const int bb1 = (r + 8) >> 11, t1 = (r + 8) & (TT - 1);
            float* dst0 = C + (((size_t)(bb0 * HH + bx)) * TT + t0) * DHH + nl;
            float* dst1 = C + (((size_t)(bb1 * HH + bx)) * TT + t1) * DHH + nl;
            float2 v0, v1;
            v0.x = acc[ma][na][0] + b0; v0.y = acc[ma][na][1] + b1;
            v1.x = acc[ma][na][2] + b0; v1.y = acc[ma][na][3] + b1;
            *(float2*)dst0 = v0;
            *(float2*)dst1 = v1;
        }
    }
}

// ---------------------------------------------------------------------------
// Output-projection TF32 GEMM (same structure, W [K,N] row-major, C [M,N]).
// ---------------------------------------------------------------------------
__global__ __launch_bounds__(256, 2) void gemm_proj(
    const float* __restrict__ A, const float* __restrict__ W,
    const float* __restrict__ bias, float* __restrict__ C)
{
    __shared__ float As[2][128][20];
    __shared__ float Bs[2][16][136];

    const int bx = blockIdx.x, by = blockIdx.y, tid = threadIdx.x;
    const int wid = tid >> 5, lane = tid & 31;
    const int gid = lane >> 2, tig = lane & 3;
    const int wr = wid >> 2, wc = wid & 3;
    const int m0 = by * 128;

    const float* Aptr = A + (size_t)m0 * KK;
    const float* Bptr = W + bx * 128;

    const int ar  = tid >> 1;
    const int ac  = (tid & 1) * 8;
    const int bkr = tid >> 4;
    const int bnc = (tid & 15) * 8;

    auto load_stage = [&](int s, int k0) {
        CP_ASYNC16(smem_u32(&As[s][ar][ac]),     Aptr + (size_t)ar * KK + k0 + ac);
        CP_ASYNC16(smem_u32(&As[s][ar][ac + 4]), Aptr + (size_t)ar * KK + k0 + ac + 4);
        CP_ASYNC16(smem_u32(&Bs[s][bkr][bnc]),     Bptr + (size_t)(k0 + bkr) * NN + bnc);
        CP_ASYNC16(smem_u32(&Bs[s][bkr][bnc + 4]), Bptr + (size_t)(k0 + bkr) * NN + bnc + 4);
    };

    float acc[4][4][4];
    #pragma unroll
    for (int i = 0; i < 4; i++)
        #pragma unroll
        for (int j = 0; j < 4; j++)
            #pragma unroll
            for (int e = 0; e < 4; e++) acc[i][j][e] = 0.f;

    load_stage(0, 0);  CP_COMMIT();
    load_stage(1, 16); CP_COMMIT();
    CP_WAIT(1);
    __syncthreads();

    int cur = 0;
    for (int k0 = 0; k0 < KK; k0 += 16) {
        #pragma unroll
        for (int ks = 0; ks < 16; ks += 8) {
            uint32_t af[4][4], bf[4][2];
            #pragma unroll
            for (int ma = 0; ma < 4; ma++) {
                const int r = wr * 64 + ma * 16 + gid;
                af[ma][0] = f2tf_u(As[cur][r][ks + tig]);
                af[ma][1] = f2tf_u(As[cur][r + 8][ks + tig]);
                af[ma][2] = f2tf_u(As[cur][r][ks + tig + 4]);
                af[ma][3] = f2tf_u(As[cur][r + 8][ks + tig + 4]);
            }
            #pragma unroll
            for (int na = 0; na < 4; na++) {
                const int n = wc * 32 + na * 8 + gid;
                bf[na][0] = f2tf_u(Bs[cur][ks + tig][n]);
                bf[na][1] = f2tf_u(Bs[cur][ks + tig + 4][n]);
            }
            #pragma unroll
            for (int ma = 0; ma < 4; ma++)
                #pragma unroll
                for (int na = 0; na < 4; na++)
                    MMA_TF32(acc[ma][na], af[ma], bf[na]);
        }
        __syncthreads();
        if (k0 + 32 < KK) load_stage(cur, k0 + 32);
        CP_COMMIT();
        CP_WAIT(1);
        __syncthreads();
        cur ^= 1;
    }

    #pragma unroll
    for (int ma = 0; ma < 4; ma++) {
        #pragma unroll
        for (int na = 0; na < 4; na++) {
            const int r  = m0 + wr * 64 + ma * 16 + gid;
            const int nl = wc * 32 + na * 8 + 2 * tig;
            const int ng = bx * 128 + nl;
            const float b0 = bias[ng], b1 = bias[ng + 1];
            float* dst0 = C + (size_t)r * NN + ng;
            float* dst1 = C + (size_t)(r + 8) * NN + ng;
            float2 v0, v1;
            v0.x = acc[ma][na][0] + b0; v0.y = acc[ma][na][1] + b1;
            v1.x = acc[ma][na][2] + b0; v1.y = acc[ma][na][3] + b1;
            *(float2*)dst0 = v0;
            *(float2*)dst1 = v1;
        }
    }
}

// ---------------------------------------------------------------------------
// Causal flash attention, tf32 MMA. Br=128, Bc=64, 256 threads (8 warps).
// Warp w owns rows w*16..w*16+15: all 64 S cols, all 128 O cols.
// Q in registers; K/V double-buffered cp.async; softmax warp-local;
// P in warp-private smem rows. One syncthreads per tile.
// ---------------------------------------------------------------------------
#define LDK 132
#define LDV 136
#define LDP 68

__global__ __launch_bounds__(256) void attn_tc(
    const float* __restrict__ Q, const float* __restrict__ Kg,
    const float* __restrict__ Vg, float* __restrict__ O)
{
    extern __shared__ float sh[];
    float* sK = sh;                   // [2][64][132]; Q staging [128][132]
    float* sV = sK + 2 * 64 * LDK;    // [2][64][136]
    float* sP = sV + 2 * 64 * LDV;    // [128][68] warp-private rows

    const int bh = blockIdx.y;
    const int q0 = blockIdx.x * 128;
    const int tid = threadIdx.x, wid = tid >> 5, lane = tid & 31;
    const int gid = lane >> 2, tig = lane & 3;
    const int wrow = wid * 16;
    const float scale = 0.08838834764831845f;   // 1/sqrt(128)

    const float* Qb = Q  + (size_t)bh * TT * DHH;
    const float* Kb = Kg + (size_t)bh * TT * DHH;
    const float* Vb = Vg + (size_t)bh * TT * DHH;

    // ---- Stage Q (scaled+tf32) into sK region, coalesced ----
    #pragma unroll
    for (int ch = 0; ch < 16; ch++) {
        const int i = tid + ch * 256;
        const int r = i >> 5, c4 = (i & 31) * 4;
        float4 v = *(const float4*)(Qb + (size_t)(q0 + r) * DHH + c4);
        v.x = f2tf(v.x * scale); v.y = f2tf(v.y * scale);
        v.z = f2tf(v.z * scale); v.w = f2tf(v.w * scale);
        *(float4*)(sK + r * LDK + c4) = v;
    }
    __syncthreads();

    // ---- Q fragments into registers: qf[16][4] ----
    uint32_t qf[16][4];
    #pragma unroll
    for (int ks = 0; ks < 16; ks++) {
        const int r0 = (wrow + gid) * LDK + ks * 8;
        const int r1 = (wrow + gid + 8) * LDK + ks * 8;
        qf[ks][0] = __float_as_uint(sK[r0 + tig]);
        qf[ks][1] = __float_as_uint(sK[r1 + tig]);
        qf[ks][2] = __float_as_uint(sK[r0 + tig + 4]);
        qf[ks][3] = __float_as_uint(sK[r1 + tig + 4]);
    }
    __syncthreads();   // frag reads done before cp.async overwrites sK

    // ---- prologue: issue K0/V0 ----
    {
        #pragma unroll
        for (int ch = 0; ch < 8; ch++) {
            const int i = tid + ch * 256;
            const int r = i >> 5, c4 = (i & 31) * 4;
            CP_ASYNC16(smem_u32(sK + r * LDK + c4), Kb + (size_t)r * DHH + c4);
            CP_ASYNC16(smem_u32(sV + r * LDV + c4), Vb + (size_t)r * DHH + c4);
        }
        CP_COMMIT();
    }

    float accO[16][4];
    #pragma unroll
    for (int na = 0; na < 16; na++)
        #pragma unroll
        for (int e = 0; e < 4; e++) accO[na][e] = 0.f;
    float m0 = -INFINITY, m1 = -INFINITY, l0 = 0.f, l1 = 0.f;

    const int nj = (q0 >> 6) + 2;
    for (int j = 0; j < nj; j++) {
        const int j0 = j * 64;
        const int buf = j & 1;
        CP_WAIT(0);
        __syncthreads();   // tile j visible; buf^1 readers (iter j-1) done

        if (j + 1 < nj) {
            float* dK = sK + (buf ^ 1) * 64 * LDK;
            float* dV = sV + (buf ^ 1) * 64 * LDV;
            const size_t row0 = (size_t)(j0 + 64);
            #pragma unroll
            for (int ch = 0; ch < 8; ch++) {
                const int i = tid + ch * 256;
                const int r = i >> 5, c4 = (i & 31) * 4;
                CP_ASYNC16(smem_u32(dK + r * LDK + c4),
                           Kb + (row0 + r) * DHH + c4);
                CP_ASYNC16(smem_u32(dV + r * LDV + c4),
                           Vb + (row0 + r) * DHH + c4);
            }
            CP_COMMIT();
        }

        // per-warp early-out on fully masked tiles
        if (j0 > q0 + wrow + 15) continue;

        const float* K0 = sK + buf * 64 * LDK;
        const float* V0 = sV + buf * 64 * LDV;

        // ---- S = Q K^T ----
        float accS[8][4];
        #pragma unroll
        for (int na = 0; na < 8; na++)
            #pragma unroll
            for (int e = 0; e < 4; e++) accS[na][e] = 0.f;

        #pragma unroll
        for (int ks = 0; ks < 16; ks++) {
            #pragma unroll
            for (int na = 0; na < 8; na++) {
                const int nb = (na * 8 + gid) * LDK + ks * 8;
                uint32_t b[2];
                b[0] = f2tf_u(K0[nb + tig]);
                b[1] = f2tf_u(K0[nb + tig + 4]);
                MMA_TF32(accS[na], qf[ks], b);
            }
        }

        // ---- causal mask ----
        if (j0 + 63 > q0 + wrow) {
            const int qi0 = q0 + wrow + gid;
            const int qi1 = qi0 + 8;
            #pragma unroll
            for (int na = 0; na < 8; na++) {
                const int c0 = j0 + na * 8 + 2 * tig;
                if (c0 > qi0)     accS[na][0] = -INFINITY;
                if (c0 + 1 > qi0) accS[na][1] = -INFINITY;
                if (c0 > qi1)     accS[na][2] = -INFINITY;
                if (c0 + 1 > qi1) accS[na][3] = -INFINITY;
            }
        }

        // ---- warp-local online softmax (rows gid, gid+8) ----
        float mt0 = -INFINITY, mt1 = -INFINITY;
        #pragma unroll
        for (int na = 0; na < 8; na++) {
            mt0 = fmaxf(mt0, fmaxf(accS[na][0], accS[na][1]));
            mt1 = fmaxf(mt1, fmaxf(accS[na][2], accS[na][3]));
        }
        mt0 = fmaxf(mt0, __shfl_xor_sync(0xffffffffu, mt0, 1));
        mt0 = fmaxf(mt0, __shfl_xor_sync(0xffffffffu, mt0, 2));
        mt1 = fmaxf(mt1, __shfl_xor_sync(0xffffffffu, mt1, 1));
        mt1 = fmaxf(mt1, __shfl_xor_sync(0xffffffffu, mt1, 2));
        const float mn0 = fmaxf(m0, mt0);
        const float mn1 = fmaxf(m1, mt1);
        const float al0 = __expf(m0 - mn0);
        const float al1 = __expf(m1 - mn1);
        m0 = mn0; m1 = mn1;
        float ls0 = 0.f, ls1 = 0.f;
        #pragma unroll
        for (int na = 0; na < 8; na++) {
            accS[na][0] = __expf(accS[na][0] - mn0);
            accS[na][1] = __expf(accS[na][1] - mn0);
            accS[na][2] = __expf(accS[na][2] - mn1);
            accS[na][3] = __expf(accS[na][3] - mn1);
            ls0 += accS[na][0] + accS[na][1];
            ls1 += accS[na][2] + accS[na][3];
        }
        ls0 += __shfl_xor_sync(0xffffffffu, ls0, 1);
        ls0 += __shfl_xor_sync(0xffffffffu, ls0, 2);
        ls1 += __shfl_xor_sync(0xffffffffu, ls1, 1);
        ls1 += __shfl_xor_sync(0xffffffffu, ls1, 2);
        l0 = l0 * al0 + ls0;
        l1 = l1 * al1 + ls1;

        // ---- P -> warp-private smem rows ----
        #pragma unroll
        for (int na = 0; na < 8; na++) {
            const int cc = na * 8 + 2 * tig;
            float2 p0, p1;
            p0.x = accS[na][0]; p0.y = accS[na][1];
            p1.x = accS[na][2]; p1.y = accS[na][3];
            *(float2*)(sP + (wrow + gid) * LDP + cc)     = p0;
            *(float2*)(sP + (wrow + gid + 8) * LDP + cc) = p1;
        }
        __syncwarp();

        // ---- rescale accO ----
        #pragma unroll
        for (int na = 0; na < 16; na++) {
            accO[na][0] *= al0; accO[na][1] *= al0;
            accO[na][2] *= al1; accO[na][3] *= al1;
        }

        // ---- O += P V ----
        #pragma unroll
        for (int ks = 0; ks < 8; ks++) {
            uint32_t a[4];
            const int r0 = (wrow + gid) * LDP + ks * 8;
            const int r1 = (wrow + gid + 8) * LDP + ks * 8;
            a[0] = f2tf_u(sP[r0 + tig]);
            a[1] = f2tf_u(sP[r1 + tig]);
            a[2] = f2tf_u(sP[r0 + tig + 4]);
            a[3] = f2tf_u(sP[r1 + tig + 4]);
            #pragma unroll
            for (int na = 0; na < 16; na++) {
                uint32_t b[2];
                b[0] = f2tf_u(V0[(ks * 8 + tig) * LDV + na * 8 + gid]);
                b[1] = f2tf_u(V0[(ks * 8 + tig + 4) * LDV + na * 8 + gid]);
                MMA_TF32(accO[na], a, b);
            }
        }
    }

    // ---- normalize + write [B, T, H*Dh] ----
    const int b = bh >> 4, h = bh & 15;
    const float inv0 = 1.f / l0;
    const float inv1 = 1.f / l1;
    const int t0 = q0 + wrow + gid;
    float* base0 = O + ((size_t)(b * TT + t0)) * NN + h * DHH;
    float* base1 = O + ((size_t)(b * TT + t0 + 8)) * NN + h * DHH;
    #pragma unroll
    for (int na = 0; na < 16; na++) {
        const int cc = na * 8 + 2 * tig;
        float2 v0, v1;
        v0.x = accO[na][0] * inv0; v0.y = accO[na][1] * inv0;
        v1.x = accO[na][2] * inv1; v1.y = accO[na][3] * inv1;
        *(float2*)(base0 + cc) = v0;
        *(float2*)(base1 + cc) = v1;
    }
}

// ---------------------------------------------------------------------------
extern "C" void kernel_launch(void* const* d_in, const int* in_sizes, int n_in,
                              void* d_out, int out_size)
{
    const float* x  = (const float*)d_in[0];
    const float* Wq = (const float*)d_in[1];
    const float* bq = (const float*)d_in[2];
    const float* Wk = (const float*)d_in[3];
    const float* bk = (const float*)d_in[4];
    const float* Wv = (const float*)d_in[5];
    const float* bv = (const float*)d_in[6];
    const float* Wp = (const float*)d_in[7];
    const float* bp = (const float*)d_in[8];
    float* out = (float*)d_out;

    float *q, *k, *v, *o;
    cudaGetSymbolAddress((void**)&q, g_q);
    cudaGetSymbolAddress((void**)&k, g_k);
    cudaGetSymbolAddress((void**)&v, g_v);
    cudaGetSymbolAddress((void**)&o, g_o);

    const int smem = (2 * 64 * LDK + 2 * 64 * LDV + 128 * LDP) * sizeof(float); // 172032
    cudaFuncSetAttribute(attn_tc, cudaFuncAttributeMaxDynamicSharedMemorySize, smem);

    gemm_qkv<<<dim3(NN / 128, MM / 128, 3), 256>>>(x, Wq, bq, Wk, bk, Wv, bv, q, k, v);

    attn_tc<<<dim3(TT / 128, BB * HH), 256, smem>>>(q, k, v, o);

    gemm_proj<<<dim3(NN / 128, MM / 128), 256>>>(o, Wp, bp, out);
}

// round 5
// speedup vs baseline: 3.6855x; 1.0643x over previous
#include <cuda_runtime.h>
#include <math.h>
#include <stdint.h>

#define BB  2
#define TT  2048
#define DD  2048
#define HH  16
#define DHH 128
#define MM  (BB*TT)    // 4096
#define NN  (HH*DHH)   // 2048
#define KK  DD         // 2048

// Scratch (allocation-free rule: __device__ globals)
__device__ float g_q[(size_t)BB*HH*TT*DHH];
__device__ float g_k[(size_t)BB*HH*TT*DHH];
__device__ float g_v[(size_t)BB*HH*TT*DHH];
__device__ float g_o[(size_t)BB*TT*NN];
__device__ float g_x[(size_t)MM*KK];          // tf32-rounded x
__device__ float g_wq[(size_t)KK*NN];         // tf32-rounded weights
__device__ float g_wk[(size_t)KK*NN];
__device__ float g_wv[(size_t)KK*NN];
__device__ float g_wp[(size_t)KK*NN];

__device__ __forceinline__ uint32_t f2tf_u(float x) {
    uint32_t r;
    asm("cvt.rna.tf32.f32 %0, %1;" : "=r"(r) : "f"(x));
    return r;
}
__device__ __forceinline__ float f2tf(float x) {
    return __uint_as_float(f2tf_u(x));
}

#define MMA_TF32(c, a, b)                                                     \
    asm volatile(                                                             \
        "mma.sync.aligned.m16n8k8.row.col.f32.tf32.tf32.f32 "                 \
        "{%0,%1,%2,%3}, {%4,%5,%6,%7}, {%8,%9}, {%0,%1,%2,%3};"               \
        : "+f"((c)[0]), "+f"((c)[1]), "+f"((c)[2]), "+f"((c)[3])              \
        : "r"((a)[0]), "r"((a)[1]), "r"((a)[2]), "r"((a)[3]),                 \
          "r"((b)[0]), "r"((b)[1]))

__device__ __forceinline__ uint32_t smem_u32(const void* p) {
    return (uint32_t)__cvta_generic_to_shared(p);
}
#define CP_ASYNC16(dst_u32, src)                                              \
    asm volatile("cp.async.cg.shared.global [%0], [%1], 16;"                  \
                 :: "r"(dst_u32), "l"(src))
#define CP_COMMIT() asm volatile("cp.async.commit_group;")
#define CP_WAIT(n)  asm volatile("cp.async.wait_group %0;" :: "n"(n))

// ---------------------------------------------------------------------------
// Pre-pass: round fp32 -> tf32 (RNA) elementwise, float4 vectorized.
// ---------------------------------------------------------------------------
__global__ __launch_bounds__(256) void round_tf32(
    const float* __restrict__ src, float* __restrict__ dst, int n4)
{
    const int i = blockIdx.x * 256 + threadIdx.x;
    if (i < n4) {
        float4 v = ((const float4*)src)[i];
        v.x = f2tf(v.x); v.y = f2tf(v.y); v.z = f2tf(v.z); v.w = f2tf(v.w);
        ((float4*)dst)[i] = v;
    }
}

// ---------------------------------------------------------------------------
// Fused QKV TF32 GEMM, cp.async double-buffered. Inputs pre-rounded.
// blockIdx.z selects weight/bias/output. Output headed [B,H,T,Dh], rounded.
// BM=BN=128, BK=16, 256 threads, warp tile 64x32.
// ---------------------------------------------------------------------------
__global__ __launch_bounds__(256, 2) void gemm_qkv(
    const float* __restrict__ A,
    const float* __restrict__ Wq, const float* __restrict__ bq,
    const float* __restrict__ Wk, const float* __restrict__ bk,
    const float* __restrict__ Wv, const float* __restrict__ bv,
    float* __restrict__ Cq, float* __restrict__ Ck, float* __restrict__ Cv)
{
    __shared__ float As[2][128][20];
    __shared__ float Bs[2][16][136];

    const int bx = blockIdx.x, by = blockIdx.y, bz = blockIdx.z;
    const int tid = threadIdx.x;
    const int wid = tid >> 5, lane = tid & 31;
    const int gid = lane >> 2, tig = lane & 3;
    const int wr = wid >> 2, wc = wid & 3;
    const int m0 = by * 128;

    const float* W    = (bz == 0) ? Wq : (bz == 1) ? Wk : Wv;
    const float* bias = (bz == 0) ? bq : (bz == 1) ? bk : bv;
    float* C          = (bz == 0) ? Cq : (bz == 1) ? Ck : Cv;

    const float* Aptr = A + (size_t)m0 * KK;
    const float* Bptr = W + (size_t)bx * ((size_t)KK * 128);

    const int ar  = tid >> 1;
    const int ac  = (tid & 1) * 8;
    const int bkr = tid >> 4;
    const int bnc = (tid & 15) * 8;

    auto load_stage = [&](int s, int k0) {
        CP_ASYNC16(smem_u32(&As[s][ar][ac]),     Aptr + (size_t)ar * KK + k0 + ac);
        CP_ASYNC16(smem_u32(&As[s][ar][ac + 4]), Aptr + (size_t)ar * KK + k0 + ac + 4);
        CP_ASYNC16(smem_u32(&Bs[s][bkr][bnc]),     Bptr + (size_t)(k0 + bkr) * 128 + bnc);
        CP_ASYNC16(smem_u32(&Bs[s][bkr][bnc + 4]), Bptr + (size_t)(k0 + bkr) * 128 + bnc + 4);
    };

    float acc[4][4][4];
    #pragma unroll
    for (int i = 0; i < 4; i++)
        #pragma unroll
        for (int j = 0; j < 4; j++)
            #pragma unroll
            for (int e = 0; e < 4; e++) acc[i][j][e] = 0.f;

    load_stage(0, 0);  CP_COMMIT();
    load_stage(1, 16); CP_COMMIT();
    CP_WAIT(1);
    __syncthreads();

    int cur = 0;
    for (int k0 = 0; k0 < KK; k0 += 16) {
        #pragma unroll
        for (int ks = 0; ks < 16; ks += 8) {
            uint32_t af[4][4], bf[4][2];
            #pragma unroll
            for (int ma = 0; ma < 4; ma++) {
                const int r = wr * 64 + ma * 16 + gid;
                af[ma][0] = __float_as_uint(As[cur][r][ks + tig]);
                af[ma][1] = __float_as_uint(As[cur][r + 8][ks + tig]);
                af[ma][2] = __float_as_uint(As[cur][r][ks + tig + 4]);
                af[ma][3] = __float_as_uint(As[cur][r + 8][ks + tig + 4]);
            }
            #pragma unroll
            for (int na = 0; na < 4; na++) {
                const int n = wc * 32 + na * 8 + gid;
                bf[na][0] = __float_as_uint(Bs[cur][ks + tig][n]);
                bf[na][1] = __float_as_uint(Bs[cur][ks + tig + 4][n]);
            }
            #pragma unroll
            for (int ma = 0; ma < 4; ma++)
                #pragma unroll
                for (int na = 0; na < 4; na++)
                    MMA_TF32(acc[ma][na], af[ma], bf[na]);
        }
        __syncthreads();
        if (k0 + 32 < KK) load_stage(cur, k0 + 32);
        CP_COMMIT();
        CP_WAIT(1);
        __syncthreads();
        cur ^= 1;
    }

    // Epilogue: bias + tf32 round (q/k/v are consumed as MMA operands downstream)
    #pragma unroll
    for (int ma = 0; ma < 4; ma++) {
        #pragma unroll
        for (int na = 0; na < 4; na++) {
            const int r  = m0 + wr * 64 + ma * 16 + gid;
            const int nl = wc * 32 + na * 8 + 2 * tig;
            const int ng = bx * 128 + nl;
            const float b0 = bias[ng], b1 = bias[ng + 1];
            const int bb0 = r >> 11,       t0 = r & (TT - 1);
            const int bb1 = (r + 8) >> 11, t1 = (r + 8) & (TT - 1);
            float* dst0 = C + (((size_t)(bb0 * HH + bx)) * TT + t0) * DHH + nl;
            float* dst1 = C + (((size_t)(bb1 * HH + bx)) * TT + t1) * DHH + nl;
            float2 v0, v1;
            v0.x = f2tf(acc[ma][na][0] + b0); v0.y = f2tf(acc[ma][na][1] + b1);
            v1.x = f2tf(acc[ma][na][2] + b0); v1.y = f2tf(acc[ma][na][3] + b1);
            *(float2*)dst0 = v0;
            *(float2*)dst1 = v1;
        }
    }
}

// ---------------------------------------------------------------------------
// Output-projection TF32 GEMM (inputs pre-rounded; output raw fp32 + bias).
// ---------------------------------------------------------------------------
__global__ __launch_bounds__(256, 2) void gemm_proj(
    const float* __restrict__ A, const float* __restrict__ W,
    const float* __restrict__ bias, float* __restrict__ C)
{
    __shared__ float As[2][128][20];
    __shared__ float Bs[2][16][136];

    const int bx = blockIdx.x, by = blockIdx.y, tid = threadIdx.x;
    const int wid = tid >> 5, lane = tid & 31;
    const int gid = lane >> 2, tig = lane & 3;
    const int wr = wid >> 2, wc = wid & 3;
    const int m0 = by * 128;

    const float* Aptr = A + (size_t)m0 * KK;
    const float* Bptr = W + bx * 128;

    const int ar  = tid >> 1;
    const int ac  = (tid & 1) * 8;
    const int bkr = tid >> 4;
    const int bnc = (tid & 15) * 8;

    auto load_stage = [&](int s, int k0) {
        CP_ASYNC16(smem_u32(&As[s][ar][ac]),     Aptr + (size_t)ar * KK + k0 + ac);
        CP_ASYNC16(smem_u32(&As[s][ar][ac + 4]), Aptr + (size_t)ar * KK + k0 + ac + 4);
        CP_ASYNC16(smem_u32(&Bs[s][bkr][bnc]),     Bptr + (size_t)(k0 + bkr) * NN + bnc);
        CP_ASYNC16(smem_u32(&Bs[s][bkr][bnc + 4]), Bptr + (size_t)(k0 + bkr) * NN + bnc + 4);
    };

    float acc[4][4][4];
    #pragma unroll
    for (int i = 0; i < 4; i++)
        #pragma unroll
        for (int j = 0; j < 4; j++)
            #pragma unroll
            for (int e = 0; e < 4; e++) acc[i][j][e] = 0.f;

    load_stage(0, 0);  CP_COMMIT();
    load_stage(1, 16); CP_COMMIT();
    CP_WAIT(1);
    __syncthreads();

    int cur = 0;
    for (int k0 = 0; k0 < KK; k0 += 16) {
        #pragma unroll
        for (int ks = 0; ks < 16; ks += 8) {
            uint32_t af[4][4], bf[4][2];
            #pragma unroll
            for (int ma = 0; ma < 4; ma++) {
                const int r = wr * 64 + ma * 16 + gid;
                af[ma][0] = __float_as_uint(As[cur][r][ks + tig]);
                af[ma][1] = __float_as_uint(As[cur][r + 8][ks + tig]);
                af[ma][2] = __float_as_uint(As[cur][r][ks + tig + 4]);
                af[ma][3] = __float_as_uint(As[cur][r + 8][ks + tig + 4]);
            }
            #pragma unroll
            for (int na = 0; na < 4; na++) {
                const int n = wc * 32 + na * 8 + gid;
                bf[na][0] = __float_as_uint(Bs[cur][ks + tig][n]);
                bf[na][1] = __float_as_uint(Bs[cur][ks + tig + 4][n]);
            }
            #pragma unroll
            for (int ma = 0; ma < 4; ma++)
                #pragma unroll
                for (int na = 0; na < 4; na++)
                    MMA_TF32(acc[ma][na], af[ma], bf[na]);
        }
        __syncthreads();
        if (k0 + 32 < KK) load_stage(cur, k0 + 32);
        CP_COMMIT();
        CP_WAIT(1);
        __syncthreads();
        cur ^= 1;
    }

    #pragma unroll
    for (int ma = 0; ma < 4; ma++) {
        #pragma unroll
        for (int na = 0; na < 4; na++) {
            const int r  = m0 + wr * 64 + ma * 16 + gid;
            const int nl = wc * 32 + na * 8 + 2 * tig;
            const int ng = bx * 128 + nl;
            const float b0 = bias[ng], b1 = bias[ng + 1];
            float* dst0 = C + (size_t)r * NN + ng;
            float* dst1 = C + (size_t)(r + 8) * NN + ng;
            float2 v0, v1;
            v0.x = acc[ma][na][0] + b0; v0.y = acc[ma][na][1] + b1;
            v1.x = acc[ma][na][2] + b0; v1.y = acc[ma][na][3] + b1;
            *(float2*)dst0 = v0;
            *(float2*)dst1 = v1;
        }
    }
}

// ---------------------------------------------------------------------------
// Causal flash attention, tf32 MMA. Br=128, Bc=64, 256 threads (8 warps).
// q/k/v arrive tf32-rounded; no cvt in mainloop. Output rounded for proj.
// ---------------------------------------------------------------------------
#define LDK 132
#define LDV 136
#define LDP 68

__global__ __launch_bounds__(256) void attn_tc(
    const float* __restrict__ Q, const float* __restrict__ Kg,
    const float* __restrict__ Vg, float* __restrict__ O)
{
    extern __shared__ float sh[];
    float* sK = sh;                   // [2][64][132]; Q staging [128][132]
    float* sV = sK + 2 * 64 * LDK;    // [2][64][136]
    float* sP = sV + 2 * 64 * LDV;    // [128][68] warp-private rows

    const int bh = blockIdx.y;
    const int q0 = blockIdx.x * 128;
    const int tid = threadIdx.x, wid = tid >> 5, lane = tid & 31;
    const int gid = lane >> 2, tig = lane & 3;
    const int wrow = wid * 16;
    const float scale = 0.08838834764831845f;   // 1/sqrt(128)

    const float* Qb = Q  + (size_t)bh * TT * DHH;
    const float* Kb = Kg + (size_t)bh * TT * DHH;
    const float* Vb = Vg + (size_t)bh * TT * DHH;

    // ---- Stage Q (scale + re-round) into sK region, coalesced ----
    #pragma unroll
    for (int ch = 0; ch < 16; ch++) {
        const int i = tid + ch * 256;
        const int r = i >> 5, c4 = (i & 31) * 4;
        float4 v = *(const float4*)(Qb + (size_t)(q0 + r) * DHH + c4);
        v.x = f2tf(v.x * scale); v.y = f2tf(v.y * scale);
        v.z = f2tf(v.z * scale); v.w = f2tf(v.w * scale);
        *(float4*)(sK + r * LDK + c4) = v;
    }
    __syncthreads();

    // ---- Q fragments into registers: qf[16][4] ----
    uint32_t qf[16][4];
    #pragma unroll
    for (int ks = 0; ks < 16; ks++) {
        const int r0 = (wrow + gid) * LDK + ks * 8;
        const int r1 = (wrow + gid + 8) * LDK + ks * 8;
        qf[ks][0] = __float_as_uint(sK[r0 + tig]);
        qf[ks][1] = __float_as_uint(sK[r1 + tig]);
        qf[ks][2] = __float_as_uint(sK[r0 + tig + 4]);
        qf[ks][3] = __float_as_uint(sK[r1 + tig + 4]);
    }
    __syncthreads();   // frag reads done before cp.async overwrites sK

    // ---- prologue: issue K0/V0 ----
    {
        #pragma unroll
        for (int ch = 0; ch < 8; ch++) {
            const int i = tid + ch * 256;
            const int r = i >> 5, c4 = (i & 31) * 4;
            CP_ASYNC16(smem_u32(sK + r * LDK + c4), Kb + (size_t)r * DHH + c4);
            CP_ASYNC16(smem_u32(sV + r * LDV + c4), Vb + (size_t)r * DHH + c4);
        }
        CP_COMMIT();
    }

    float accO[16][4];
    #pragma unroll
    for (int na = 0; na < 16; na++)
        #pragma unroll
        for (int e = 0; e < 4; e++) accO[na][e] = 0.f;
    float m0 = -INFINITY, m1 = -INFINITY, l0 = 0.f, l1 = 0.f;

    const int nj = (q0 >> 6) + 2;
    for (int j = 0; j < nj; j++) {
        const int j0 = j * 64;
        const int buf = j & 1;
        CP_WAIT(0);
        __syncthreads();   // tile j visible; buf^1 readers (iter j-1) done

        if (j + 1 < nj) {
            float* dK = sK + (buf ^ 1) * 64 * LDK;
            float* dV = sV + (buf ^ 1) * 64 * LDV;
            const size_t row0 = (size_t)(j0 + 64);
            #pragma unroll
            for (int ch = 0; ch < 8; ch++) {
                const int i = tid + ch * 256;
                const int r = i >> 5, c4 = (i & 31) * 4;
                CP_ASYNC16(smem_u32(dK + r * LDK + c4),
                           Kb + (row0 + r) * DHH + c4);
                CP_ASYNC16(smem_u32(dV + r * LDV + c4),
                           Vb + (row0 + r) * DHH + c4);
            }
            CP_COMMIT();
        }

        // per-warp early-out on fully masked tiles
        if (j0 > q0 + wrow + 15) continue;

        const float* K0 = sK + buf * 64 * LDK;
        const float* V0 = sV + buf * 64 * LDV;

        // ---- S = Q K^T ----
        float accS[8][4];
        #pragma unroll
        for (int na = 0; na < 8; na++)
            #pragma unroll
            for (int e = 0; e < 4; e++) accS[na][e] = 0.f;

        #pragma unroll
        for (int ks = 0; ks < 16; ks++) {
            #pragma unroll
            for (int na = 0; na < 8; na++) {
                const int nb = (na * 8 + gid) * LDK + ks * 8;
                uint32_t b[2];
                b[0] = __float_as_uint(K0[nb + tig]);
                b[1] = __float_as_uint(K0[nb + tig + 4]);
                MMA_TF32(accS[na], qf[ks], b);
            }
        }

        // ---- causal mask ----
        if (j0 + 63 > q0 + wrow) {
            const int qi0 = q0 + wrow + gid;
            const int qi1 = qi0 + 8;
            #pragma unroll
            for (int na = 0; na < 8; na++) {
                const int c0 = j0 + na * 8 + 2 * tig;
                if (c0 > qi0)     accS[na][0] = -INFINITY;
                if (c0 + 1 > qi0) accS[na][1] = -INFINITY;
                if (c0 > qi1)     accS[na][2] = -INFINITY;
                if (c0 + 1 > qi1) accS[na][3] = -INFINITY;
            }
        }

        // ---- warp-local online softmax (rows gid, gid+8) ----
        float mt0 = -INFINITY, mt1 = -INFINITY;
        #pragma unroll
        for (int na = 0; na < 8; na++) {
            mt0 = fmaxf(mt0, fmaxf(accS[na][0], accS[na][1]));
            mt1 = fmaxf(mt1, fmaxf(accS[na][2], accS[na][3]));
        }
        mt0 = fmaxf(mt0, __shfl_xor_sync(0xffffffffu, mt0, 1));
        mt0 = fmaxf(mt0, __shfl_xor_sync(0xffffffffu, mt0, 2));
        mt1 = fmaxf(mt1, __shfl_xor_sync(0xffffffffu, mt1, 1));
        mt1 = fmaxf(mt1, __shfl_xor_sync(0xffffffffu, mt1, 2));
        const float mn0 = fmaxf(m0, mt0);
        const float mn1 = fmaxf(m1, mt1);
        const float al0 = __expf(m0 - mn0);
        const float al1 = __expf(m1 - mn1);
        m0 = mn0; m1 = mn1;
        float ls0 = 0.f, ls1 = 0.f;
        #pragma unroll
        for (int na = 0; na < 8; na++) {
            accS[na][0] = __expf(accS[na][0] - mn0);
            accS[na][1] = __expf(accS[na][1] - mn0);
            accS[na][2] = __expf(accS[na][2] - mn1);
            accS[na][3] = __expf(accS[na][3] - mn1);
            ls0 += accS[na][0] + accS[na][1];
            ls1 += accS[na][2] + accS[na][3];
        }
        ls0 += __shfl_xor_sync(0xffffffffu, ls0, 1);
        ls0 += __shfl_xor_sync(0xffffffffu, ls0, 2);
        ls1 += __shfl_xor_sync(0xffffffffu, ls1, 1);
        ls1 += __shfl_xor_sync(0xffffffffu, ls1, 2);
        l0 = l0 * al0 + ls0;
        l1 = l1 * al1 + ls1;

        // ---- P -> warp-private smem rows (tf32-rounded once) ----
        #pragma unroll
        for (int na = 0; na < 8; na++) {
            const int cc = na * 8 + 2 * tig;
            float2 p0, p1;
            p0.x = f2tf(accS[na][0]); p0.y = f2tf(accS[na][1]);
            p1.x = f2tf(accS[na][2]); p1.y = f2tf(accS[na][3]);
            *(float2*)(sP + (wrow + gid) * LDP + cc)     = p0;
            *(float2*)(sP + (wrow + gid + 8) * LDP + cc) = p1;
        }
        __syncwarp();

        // ---- rescale accO ----
        #pragma unroll
        for (int na = 0; na < 16; na++) {
            accO[na][0] *= al0; accO[na][1] *= al0;
            accO[na][2] *= al1; accO[na][3] *= al1;
        }

        // ---- O += P V ----
        #pragma unroll
        for (int ks = 0; ks < 8; ks++) {
            uint32_t a[4];
            const int r0 = (wrow + gid) * LDP + ks * 8;
            const int r1 = (wrow + gid + 8) * LDP + ks * 8;
            a[0] = __float_as_uint(sP[r0 + tig]);
            a[1] = __float_as_uint(sP[r1 + tig]);
            a[2] = __float_as_uint(sP[r0 + tig + 4]);
            a[3] = __float_as_uint(sP[r1 + tig + 4]);
            #pragma unroll
            for (int na = 0; na < 16; na++) {
                uint32_t b[2];
                b[0] = __float_as_uint(V0[(ks * 8 + tig) * LDV + na * 8 + gid]);
                b[1] = __float_as_uint(V0[(ks * 8 + tig + 4) * LDV + na * 8 + gid]);
                MMA_TF32(accO[na], a, b);
            }
        }
    }

    // ---- normalize + round + write [B, T, H*Dh] (feeds gemm_proj) ----
    const int b = bh >> 4, h = bh & 15;
    const float inv0 = 1.f / l0;
    const float inv1 = 1.f / l1;
    const int t0 = q0 + wrow + gid;
    float* base0 = O + ((size_t)(b * TT + t0)) * NN + h * DHH;
    float* base1 = O + ((size_t)(b * TT + t0 + 8)) * NN + h * DHH;
    #pragma unroll
    for (int na = 0; na < 16; na++) {
        const int cc = na * 8 + 2 * tig;
        float2 v0, v1;
        v0.x = f2tf(accO[na][0] * inv0); v0.y = f2tf(accO[na][1] * inv0);
        v1.x = f2tf(accO[na][2] * inv1); v1.y = f2tf(accO[na][3] * inv1);
        *(float2*)(base0 + cc) = v0;
        *(float2*)(base1 + cc) = v1;
    }
}

// ---------------------------------------------------------------------------
extern "C" void kernel_launch(void* const* d_in, const int* in_sizes, int n_in,
                              void* d_out, int out_size)
{
    const float* x  = (const float*)d_in[0];
    const float* Wq = (const float*)d_in[1];
    const float* bq = (const float*)d_in[2];
    const float* Wk = (const float*)d_in[3];
    const float* bk = (const float*)d_in[4];
    const float* Wv = (const float*)d_in[5];
    const float* bv = (const float*)d_in[6];
    const float* Wp = (const float*)d_in[7];
    const float* bp = (const float*)d_in[8];
    float* out = (float*)d_out;

    float *q, *k, *v, *o, *xr, *wq, *wk, *wv, *wp;
    cudaGetSymbolAddress((void**)&q,  g_q);
    cudaGetSymbolAddress((void**)&k,  g_k);
    cudaGetSymbolAddress((void**)&v,  g_v);
    cudaGetSymbolAddress((void**)&o,  g_o);
    cudaGetSymbolAddress((void**)&xr, g_x);
    cudaGetSymbolAddress((void**)&wq, g_wq);
    cudaGetSymbolAddress((void**)&wk, g_wk);
    cudaGetSymbolAddress((void**)&wv, g_wv);
    cudaGetSymbolAddress((void**)&wp, g_wp);

    const int smem = (2 * 64 * LDK + 2 * 64 * LDV + 128 * LDP) * sizeof(float); // 172032
    cudaFuncSetAttribute(attn_tc, cudaFuncAttributeMaxDynamicSharedMemorySize, smem);

    // Pre-round inputs to tf32 once
    const int nx4 = (MM * KK) / 4, nw4 = (KK * NN) / 4;
    round_tf32<<<(nx4 + 255) / 256, 256>>>(x,  xr, nx4);
    round_tf32<<<(nw4 + 255) / 256, 256>>>(Wq, wq, nw4);
    round_tf32<<<(nw4 + 255) / 256, 256>>>(Wk, wk, nw4);
    round_tf32<<<(nw4 + 255) / 256, 256>>>(Wv, wv, nw4);
    round_tf32<<<(nw4 + 255) / 256, 256>>>(Wp, wp, nw4);

    gemm_qkv<<<dim3(NN / 128, MM / 128, 3), 256>>>(xr, wq, bq, wk, bk, wv, bv, q, k, v);

    attn_tc<<<dim3(TT / 128, BB * HH), 256, smem>>>(q, k, v, o);

    gemm_proj<<<dim3(NN / 128, MM / 128), 256>>>(o, wp, bp, out);
}